// round 12
// baseline (speedup 1.0000x reference)
#include <cuda_runtime.h>
#include <cuda_bf16.h>

// Radius graph (r=5, K=32, self-loops) for 96 molecules x 128 atoms.
// Output layout (float32), NK = N*K:
//   [0,NK)      src indices (as float)
//   [NK,2NK)    dst indices (as float)
//   [2NK,3NK)   edge weights
//   [3NK,6NK)   edge vectors, row-major [NK][3]

constexpr int MOL = 128;              // atoms per molecule (contiguous batch)
constexpr int K = 32;                 // max neighbors
constexpr float R2 = 25.0f;           // cutoff^2
constexpr int WARPS_PER_BLOCK = 8;    // 8 nodes per block
constexpr int BLOCK = 32 * WARPS_PER_BLOCK;

typedef unsigned long long u64;
constexpr u64 SENT = 0xFFFFFFFFFFFFFFFFull;

// In-register compare-exchange (both outputs). Equal keys are identical
// (index embedded), so a single < predicate suffices.
__device__ __forceinline__ void ce(u64& a, u64& b, bool asc) {
    bool sw = (b < a) == asc;
    u64 ta = a, tb = b;
    a = sw ? tb : ta;
    b = sw ? ta : tb;
}

// Shuffle compare-exchange: keep min if keepmin, else max.
__device__ __forceinline__ void sce(u64& x, int d, bool keepmin) {
    u64 o = __shfl_xor_sync(0xFFFFFFFFu, x, d);
    bool take = (o < x) == keepmin;
    x = take ? o : x;
}

__global__ __launch_bounds__(BLOCK)
void radius_graph_kernel(const float* __restrict__ pos,
                         float* __restrict__ out, int N) {
    __shared__ float sx[MOL], sy[MOL], sz[MOL], ssq[MOL];
    __shared__ u64 scratch[WARPS_PER_BLOCK][64];
    const int NKtot = N * K;
    const int tid  = threadIdx.x;
    const int lane = tid & 31;
    const int w    = tid >> 5;
    const int blocksPerMol = MOL / WARPS_PER_BLOCK;   // 16
    const int m = blockIdx.x / blocksPerMol;
    const int g = blockIdx.x % blocksPerMol;
    const float* pm = pos + (size_t)m * MOL * 3;

    // Stage molecule positions into SMEM (SoA).
    for (int idx = tid; idx < MOL * 3; idx += BLOCK) {
        float v = pm[idx];
        int a = idx / 3, c = idx - 3 * a;
        if (c == 0)      sx[a] = v;
        else if (c == 1) sy[a] = v;
        else             sz[a] = v;
    }
    __syncthreads();
    if (tid < MOL) {
        float x = sx[tid], y = sy[tid], z = sz[tid];
        // mirror XLA+ptxas (-fmad=true) contraction of jnp.sum(pos*pos):
        // fma(z,z, fma(y,y, x*x))
        ssq[tid] = __fmaf_rn(z, z, __fmaf_rn(y, y, __fmul_rn(x, x)));
    }
    __syncthreads();

    const int il = g * WARPS_PER_BLOCK + w;   // local node id 0..127
    const int i  = m * MOL + il;              // global node id
    const float xi = sx[il], yi = sy[il], zi = sz[il], sqi = ssq[il];

    // Build 128 keys: (d2_bits << 32) | j_local  (out-of-radius -> SENT).
    u64 r[4];
#pragma unroll
    for (int v = 0; v < 4; v++) {
        int jl = v * 32 + lane;
        // cublas/contracted FFMA k-ascending chain: fma(z,z', fma(y,y', x*x'))
        float dot = __fmaf_rn(zi, sz[jl],
                    __fmaf_rn(yi, sy[jl], __fmul_rn(xi, sx[jl])));
        float a  = __fadd_rn(sqi, ssq[jl]);
        float d2 = __fadd_rn(a, -2.0f * dot);   // -2*dot exact scaling
        d2 = fmaxf(d2, 0.0f);
        r[v] = (d2 <= R2)
                 ? ((((u64)__float_as_uint(d2)) << 32) | (unsigned)jl)
                 : SENT;
    }

    const unsigned FULL = 0xFFFFFFFFu;

    // Warp-uniform candidate count (one node per warp).
    unsigned b0 = __ballot_sync(FULL, r[0] != SENT);
    unsigned b1 = __ballot_sync(FULL, r[1] != SENT);
    unsigned b2 = __ballot_sync(FULL, r[2] != SENT);
    unsigned b3 = __ballot_sync(FULL, r[3] != SENT);
    int c0 = __popc(b0), c1 = __popc(b1), c2 = __popc(b2), c3 = __popc(b3);
    int n_valid = c0 + c1 + c2 + c3;   // >= 1 (self always in radius)

    u64 key;   // rank-`lane` result

    if (n_valid <= 64) {
        // Compact valid keys into scratch[w][0..n_valid). Order within the
        // scratch is irrelevant: the sort below establishes the order.
        unsigned lt = (1u << lane) - 1u;
        if (r[0] != SENT) scratch[w][__popc(b0 & lt)] = r[0];
        if (r[1] != SENT) scratch[w][c0 + __popc(b1 & lt)] = r[1];
        if (r[2] != SENT) scratch[w][c0 + c1 + __popc(b2 & lt)] = r[2];
        if (r[3] != SENT) scratch[w][c0 + c1 + c2 + __popc(b3 & lt)] = r[3];
        __syncwarp(FULL);

        if (n_valid <= 32) {
            // Bitonic sort-32, one key per lane; rank = lane afterwards.
            u64 x = (lane < n_valid) ? scratch[w][lane] : SENT;
#pragma unroll
            for (int k = 2; k <= 32; k <<= 1) {
#pragma unroll
                for (int j = k >> 1; j > 0; j >>= 1) {
                    bool keepmin = (((lane & k) == 0) == ((lane & j) == 0));
                    sce(x, j, keepmin);
                }
            }
            key = x;
        } else {
            // Bitonic sort-64, lane-major slots e = 2*lane + v.
            // Initial slot assignment is arbitrary (it's a full sort), so
            // load conflict-free: s0 <- scratch[lane], s1 <- scratch[lane+32].
            u64 s0 = (lane      < n_valid) ? scratch[w][lane]      : SENT;
            u64 s1 = (lane + 32 < n_valid) ? scratch[w][lane + 32] : SENT;
            // k=2 (j=1): register CE, dir from e&2 -> lane bit0.
            ce(s0, s1, (lane & 1) == 0);
#pragma unroll
            for (int k = 4; k <= 64; k <<= 1) {
                bool asc = ((lane & (k >> 1)) == 0);  // k=64 -> always asc
#pragma unroll
                for (int j = k >> 1; j >= 2; j >>= 1) {
                    int d = j >> 1;
                    bool keepmin = (asc == ((lane & d) == 0));
                    sce(s0, d, keepmin);
                    sce(s1, d, keepmin);
                }
                ce(s0, s1, asc);                       // j=1
            }
            // Rank e at lane e>>1, reg e&1; lane L takes rank L.
            u64 t0 = __shfl_sync(FULL, s0, lane >> 1);
            u64 t1 = __shfl_sync(FULL, s1, lane >> 1);
            key = (lane & 1) ? t1 : t0;
        }
    } else {
        // Full 128-element bitonic sort, lane-major slots e = 4*lane + v.
        // Stage k=2 (j=1): dir from e&2 = v&2.
        ce(r[0], r[1], true);
        ce(r[2], r[3], false);
        // Stage k=4 (j=2,1): dir from e&4 -> lane bit0.
        {
            bool asc = ((lane & 1) == 0);
            ce(r[0], r[2], asc); ce(r[1], r[3], asc);
            ce(r[0], r[1], asc); ce(r[2], r[3], asc);
        }
        // Stages k=8..128.
#pragma unroll
        for (int k = 8; k <= 128; k <<= 1) {
            bool asc = ((lane & (k >> 2)) == 0);   // k=128 -> always asc
#pragma unroll
            for (int j = k >> 1; j >= 4; j >>= 1) {
                int d = j >> 2;
                bool keepmin = (asc == ((lane & d) == 0));
#pragma unroll
                for (int v = 0; v < 4; v++) sce(r[v], d, keepmin);
            }
            ce(r[0], r[2], asc); ce(r[1], r[3], asc);
            ce(r[0], r[1], asc); ce(r[2], r[3], asc);
        }
        // Rank e at lane e>>2, reg e&3; lane L takes rank L.
        u64 t0 = __shfl_sync(FULL, r[0], lane >> 2);
        u64 t1 = __shfl_sync(FULL, r[1], lane >> 2);
        u64 t2 = __shfl_sync(FULL, r[2], lane >> 2);
        u64 t3 = __shfl_sync(FULL, r[3], lane >> 2);
        int s = lane & 3;
        key = (s == 0) ? t0 : (s == 1) ? t1 : (s == 2) ? t2 : t3;
    }

    // Emit edge `lane` of node i.
    int eout = i * K + lane;
    int dstj;
    float wgt, vx, vy, vz;
    if (key == SENT) {
        dstj = i; wgt = 0.0f; vx = vy = vz = 0.0f;   // padding self-loop
    } else {
        int jl = (int)(unsigned)(key & 0xffffffffull);
        dstj = m * MOL + jl;
        vx = xi - sx[jl];
        vy = yi - sy[jl];
        vz = zi - sz[jl];
        if (dstj == i) {
            wgt = 0.0f;   // genuine self-loop (vec exactly 0)
        } else {
            // mirror XLA+ptxas contraction of jnp.sum(vec*vec):
            // fma(vz,vz, fma(vy,vy, vx*vx))
            float ss = __fmaf_rn(vz, vz,
                       __fmaf_rn(vy, vy, __fmul_rn(vx, vx)));
            wgt = sqrtf(ss);
        }
    }

    // Streaming (evict-first) stores: output is write-once, never re-read.
    __stcs(&out[eout],             (float)i);
    __stcs(&out[NKtot + eout],     (float)dstj);
    __stcs(&out[2 * NKtot + eout], wgt);
    float* vb = out + 3 * (size_t)NKtot + 3 * (size_t)eout;
    __stcs(&vb[0], vx);
    __stcs(&vb[1], vy);
    __stcs(&vb[2], vz);
}

extern "C" void kernel_launch(void* const* d_in, const int* in_sizes, int n_in,
                              void* d_out, int out_size) {
    const float* pos = (const float*)d_in[0];
    // in_sizes[1] = N (batch array length); batch is contiguous 128-atom blocks.
    int N = in_sizes[1];
    int grid = (N / MOL) * (MOL / WARPS_PER_BLOCK);
    radius_graph_kernel<<<grid, BLOCK>>>(pos, (float*)d_out, N);
}

// round 14
// speedup vs baseline: 1.0340x; 1.0340x over previous
#include <cuda_runtime.h>
#include <cuda_bf16.h>

// Radius graph (r=5, K=32, self-loops) for 96 molecules x 128 atoms.
// Output layout (float32), NK = N*K:
//   [0,NK) src | [NK,2NK) dst | [2NK,3NK) weight | [3NK,6NK) vec[NK][3]

constexpr int MOL = 128;
constexpr int K = 32;
constexpr float R2 = 25.0f;
constexpr int WARPS_PER_BLOCK = 8;
constexpr int BLOCK = 32 * WARPS_PER_BLOCK;
constexpr int GRID0 = 152 * 8;        // one full resident wave on GB300 (152 SMs)

typedef unsigned long long u64;
constexpr u64 SENT = 0xFFFFFFFFFFFFFFFFull;

__device__ unsigned g_ticket;         // persistent-work ticket (module-scope, no alloc)

__global__ void reset_ticket(unsigned start) { g_ticket = start; }

// In-register compare-exchange (both outputs). Equal keys are identical
// (index embedded), so a single < predicate suffices.
__device__ __forceinline__ void ce(u64& a, u64& b, bool asc) {
    bool sw = (b < a) == asc;
    u64 ta = a, tb = b;
    a = sw ? tb : ta;
    b = sw ? ta : tb;
}

// Shuffle compare-exchange: keep min if keepmin, else max.
__device__ __forceinline__ void sce(u64& x, int d, bool keepmin) {
    u64 o = __shfl_xor_sync(0xFFFFFFFFu, x, d);
    bool take = (o < x) == keepmin;
    x = take ? o : x;
}

__global__ __launch_bounds__(BLOCK, 8)
void radius_graph_kernel(const float* __restrict__ pos,
                         float* __restrict__ out, int N) {
    __shared__ float sx[MOL], sy[MOL], sz[MOL], ssq[MOL];
    __shared__ u64 scratch[WARPS_PER_BLOCK][64];
    __shared__ unsigned sNext;
    const int NKtot = N * K;
    const int tid  = threadIdx.x;
    const int lane = tid & 31;
    const int w    = tid >> 5;
    const unsigned nUnits = (unsigned)((N / MOL) * (MOL / WARPS_PER_BLOCK)); // 1536
    const unsigned FULL = 0xFFFFFFFFu;

    unsigned unit = blockIdx.x;
    while (unit < nUnits) {
        const int m = unit >> 4;          // molecule (16 units per molecule)
        const int g = unit & 15;
        const float* pm = pos + (size_t)m * MOL * 3;

        // Stage molecule positions into SMEM (SoA).
        for (int idx = tid; idx < MOL * 3; idx += BLOCK) {
            float v = pm[idx];
            int a = idx / 3, c = idx - 3 * a;
            if (c == 0)      sx[a] = v;
            else if (c == 1) sy[a] = v;
            else             sz[a] = v;
        }
        __syncthreads();
        if (tid < MOL) {
            float x = sx[tid], y = sy[tid], z = sz[tid];
            // mirror XLA+ptxas (-fmad) contraction of jnp.sum(pos*pos)
            ssq[tid] = __fmaf_rn(z, z, __fmaf_rn(y, y, __fmul_rn(x, x)));
        }
        __syncthreads();

        const int il = g * WARPS_PER_BLOCK + w;   // local node id 0..127
        const int i  = m * MOL + il;              // global node id
        const float xi = sx[il], yi = sy[il], zi = sz[il], sqi = ssq[il];

        // Build 128 keys: (d2_bits << 32) | j_local  (out-of-radius -> SENT).
        u64 r[4];
#pragma unroll
        for (int v = 0; v < 4; v++) {
            int jl = v * 32 + lane;
            float dot = __fmaf_rn(zi, sz[jl],
                        __fmaf_rn(yi, sy[jl], __fmul_rn(xi, sx[jl])));
            float a  = __fadd_rn(sqi, ssq[jl]);
            float d2 = __fadd_rn(a, -2.0f * dot);
            d2 = fmaxf(d2, 0.0f);
            r[v] = (d2 <= R2)
                     ? ((((u64)__float_as_uint(d2)) << 32) | (unsigned)jl)
                     : SENT;
        }

        // Warp-uniform candidate count.
        unsigned b0 = __ballot_sync(FULL, r[0] != SENT);
        unsigned b1 = __ballot_sync(FULL, r[1] != SENT);
        unsigned b2 = __ballot_sync(FULL, r[2] != SENT);
        unsigned b3 = __ballot_sync(FULL, r[3] != SENT);
        int c0 = __popc(b0), c1 = __popc(b1), c2 = __popc(b2), c3 = __popc(b3);
        int n_valid = c0 + c1 + c2 + c3;

        u64 key;

        if (n_valid <= 64) {
            // Compact valid keys into scratch[w][0..n_valid).
            unsigned lt = (1u << lane) - 1u;
            if (r[0] != SENT) scratch[w][__popc(b0 & lt)] = r[0];
            if (r[1] != SENT) scratch[w][c0 + __popc(b1 & lt)] = r[1];
            if (r[2] != SENT) scratch[w][c0 + c1 + __popc(b2 & lt)] = r[2];
            if (r[3] != SENT) scratch[w][c0 + c1 + c2 + __popc(b3 & lt)] = r[3];
            __syncwarp(FULL);

            if (n_valid <= 32) {
                // Bitonic sort-32; rank = lane afterwards.
                u64 x = (lane < n_valid) ? scratch[w][lane] : SENT;
#pragma unroll
                for (int k = 2; k <= 32; k <<= 1) {
#pragma unroll
                    for (int j = k >> 1; j > 0; j >>= 1) {
                        bool keepmin = (((lane & k) == 0) == ((lane & j) == 0));
                        sce(x, j, keepmin);
                    }
                }
                key = x;
            } else {
                // Bitonic sort-64, lane-major slots e = 2*lane + v.
                u64 s0 = (lane      < n_valid) ? scratch[w][lane]      : SENT;
                u64 s1 = (lane + 32 < n_valid) ? scratch[w][lane + 32] : SENT;
                ce(s0, s1, (lane & 1) == 0);
#pragma unroll
                for (int k = 4; k <= 64; k <<= 1) {
                    bool asc = ((lane & (k >> 1)) == 0);
#pragma unroll
                    for (int j = k >> 1; j >= 2; j >>= 1) {
                        int d = j >> 1;
                        bool keepmin = (asc == ((lane & d) == 0));
                        sce(s0, d, keepmin);
                        sce(s1, d, keepmin);
                    }
                    ce(s0, s1, asc);
                }
                u64 t0 = __shfl_sync(FULL, s0, lane >> 1);
                u64 t1 = __shfl_sync(FULL, s1, lane >> 1);
                key = (lane & 1) ? t1 : t0;
            }
        } else {
            // Full 128-element bitonic sort, lane-major slots e = 4*lane + v.
            ce(r[0], r[1], true);
            ce(r[2], r[3], false);
            {
                bool asc = ((lane & 1) == 0);
                ce(r[0], r[2], asc); ce(r[1], r[3], asc);
                ce(r[0], r[1], asc); ce(r[2], r[3], asc);
            }
#pragma unroll
            for (int k = 8; k <= 128; k <<= 1) {
                bool asc = ((lane & (k >> 2)) == 0);
#pragma unroll
                for (int j = k >> 1; j >= 4; j >>= 1) {
                    int d = j >> 2;
                    bool keepmin = (asc == ((lane & d) == 0));
#pragma unroll
                    for (int v = 0; v < 4; v++) sce(r[v], d, keepmin);
                }
                ce(r[0], r[2], asc); ce(r[1], r[3], asc);
                ce(r[0], r[1], asc); ce(r[2], r[3], asc);
            }
            u64 t0 = __shfl_sync(FULL, r[0], lane >> 2);
            u64 t1 = __shfl_sync(FULL, r[1], lane >> 2);
            u64 t2 = __shfl_sync(FULL, r[2], lane >> 2);
            u64 t3 = __shfl_sync(FULL, r[3], lane >> 2);
            int s = lane & 3;
            key = (s == 0) ? t0 : (s == 1) ? t1 : (s == 2) ? t2 : t3;
        }

        // Emit edge `lane` of node i.
        int eout = i * K + lane;
        int dstj;
        float wgt, vx, vy, vz;
        if (key == SENT) {
            dstj = i; wgt = 0.0f; vx = vy = vz = 0.0f;   // padding self-loop
        } else {
            int jl = (int)(unsigned)(key & 0xffffffffull);
            dstj = m * MOL + jl;
            vx = xi - sx[jl];
            vy = yi - sy[jl];
            vz = zi - sz[jl];
            if (dstj == i) {
                wgt = 0.0f;
            } else {
                // mirror XLA+ptxas contraction of jnp.sum(vec*vec)
                float ss = __fmaf_rn(vz, vz,
                           __fmaf_rn(vy, vy, __fmul_rn(vx, vx)));
                wgt = sqrtf(ss);
            }
        }

        __stcs(&out[eout],             (float)i);
        __stcs(&out[NKtot + eout],     (float)dstj);
        __stcs(&out[2 * NKtot + eout], wgt);
        float* vb = out + 3 * (size_t)NKtot + 3 * (size_t)eout;
        __stcs(&vb[0], vx);
        __stcs(&vb[1], vy);
        __stcs(&vb[2], vz);

        // Grab next work unit (work-conserving; output depends only on unit).
        __syncthreads();
        if (tid == 0) sNext = atomicAdd(&g_ticket, 1u);
        __syncthreads();
        unit = sNext;
    }
}

extern "C" void kernel_launch(void* const* d_in, const int* in_sizes, int n_in,
                              void* d_out, int out_size) {
    const float* pos = (const float*)d_in[0];
    int N = in_sizes[1];
    int nUnits = (N / MOL) * (MOL / WARPS_PER_BLOCK);
    int grid = (GRID0 < nUnits) ? GRID0 : nUnits;
    reset_ticket<<<1, 1>>>((unsigned)grid);
    radius_graph_kernel<<<grid, BLOCK>>>(pos, (float*)d_out, N);
}